// round 1
// baseline (speedup 1.0000x reference)
#include <cuda_runtime.h>
#include <math.h>

#define NLIG  10000
#define NPROT 40000
#define NN    50000
#define EE    400000
#define BBG   512
#define HDIM  256
#define FLIG  74
#define FPROT 1280

// ---------------- scratch (static device globals; no runtime alloc) ----------
__device__ float g_x[NN * HDIM];      // projection output / layer2 output
__device__ float g_h[NN * HDIM];      // per-layer GEMM output (pre-aggregation)
__device__ float g_y[NN * HDIM];      // layer1 aggregated output
__device__ float g_atts[NN * 4];
__device__ float g_attd[NN * 4];
__device__ int   g_cnt[NN];
__device__ int   g_cur[NN];
__device__ int   g_off[NN + 1];
__device__ int   g_csr[EE];
__device__ int   g_gstart[BBG + 1];
__device__ float g_pool[BBG * HDIM];

// ---------------- SGEMM: C[M,N] = A[M,K] @ B[K,N], N multiple of 128 ---------
// 128x128 block tile, BK=8, 256 threads, 8x8 microtile.
__global__ void sgemm128(const float* __restrict__ A, const float* __restrict__ B,
                         float* __restrict__ C, int M, int N, int K) {
    __shared__ float As[8][128];
    __shared__ float Bs[8][128];
    const int tid = threadIdx.x;
    const int tx = tid & 15;          // 0..15  -> col subtile
    const int ty = tid >> 4;          // 0..15  -> row subtile
    const int rowBase = blockIdx.y * 128;
    const int colBase = blockIdx.x * 128;

    const int aRow = tid >> 1;            // 0..127
    const int aCol0 = (tid & 1) * 4;      // 0 or 4
    const int bRow = tid >> 5;            // 0..7
    const int bCol = (tid & 31) * 4;      // 0..124

    float acc[8][8];
#pragma unroll
    for (int i = 0; i < 8; i++)
#pragma unroll
        for (int j = 0; j < 8; j++) acc[i][j] = 0.f;

    for (int k0 = 0; k0 < K; k0 += 8) {
        // load A tile (transposed into smem), scalar loads with guards
        {
            int gr = rowBase + aRow;
#pragma unroll
            for (int j = 0; j < 4; j++) {
                int k = k0 + aCol0 + j;
                float v = 0.f;
                if (gr < M && k < K) v = A[(long)gr * K + k];
                As[aCol0 + j][aRow] = v;
            }
        }
        // load B tile, float4 (N multiple of 4 always; guard k)
        {
            int k = k0 + bRow;
            float4 v = make_float4(0.f, 0.f, 0.f, 0.f);
            if (k < K) v = *(const float4*)(B + (long)k * N + colBase + bCol);
            *(float4*)&Bs[bRow][bCol] = v;
        }
        __syncthreads();
#pragma unroll
        for (int kk = 0; kk < 8; kk++) {
            float a[8], b[8];
#pragma unroll
            for (int i = 0; i < 8; i++) a[i] = As[kk][ty * 8 + i];
#pragma unroll
            for (int j = 0; j < 8; j++) b[j] = Bs[kk][tx * 8 + j];
#pragma unroll
            for (int i = 0; i < 8; i++)
#pragma unroll
                for (int j = 0; j < 8; j++) acc[i][j] += a[i] * b[j];
        }
        __syncthreads();
    }

#pragma unroll
    for (int i = 0; i < 8; i++) {
        int gr = rowBase + ty * 8 + i;
        if (gr >= M) continue;
        float* crow = C + (long)gr * N + colBase + tx * 8;
        *(float4*)(crow)     = make_float4(acc[i][0], acc[i][1], acc[i][2], acc[i][3]);
        *(float4*)(crow + 4) = make_float4(acc[i][4], acc[i][5], acc[i][6], acc[i][7]);
    }
}

// ---------------- CSR build ----------------
__global__ void count_edges(const int* __restrict__ dst) {
    int i = blockIdx.x * blockDim.x + threadIdx.x;
    if (i < EE) atomicAdd(&g_cnt[dst[i]], 1);
}

__global__ void scan_kernel() {
    __shared__ int wsum[32];
    const int tid = threadIdx.x, lane = tid & 31, wid = tid >> 5;
    int carry = 0;
    for (int base = 0; base < NN; base += 1024) {
        int i = base + tid;
        int v = (i < NN) ? g_cnt[i] : 0;
        int x = v;
#pragma unroll
        for (int o = 1; o < 32; o <<= 1) {
            int y = __shfl_up_sync(0xffffffffu, x, o);
            if (lane >= o) x += y;
        }
        if (lane == 31) wsum[wid] = x;
        __syncthreads();
        if (wid == 0) {
            int s = wsum[lane];
#pragma unroll
            for (int o = 1; o < 32; o <<= 1) {
                int y = __shfl_up_sync(0xffffffffu, s, o);
                if (lane >= o) s += y;
            }
            wsum[lane] = s;
        }
        __syncthreads();
        int woff = wid ? wsum[wid - 1] : 0;
        if (i < NN) g_off[i] = carry + woff + x - v;   // exclusive
        int total = wsum[31];
        __syncthreads();
        carry += total;
    }
    if (tid == 0) g_off[NN] = carry;
}

__global__ void scatter_edges(const int* __restrict__ src, const int* __restrict__ dst) {
    int i = blockIdx.x * blockDim.x + threadIdx.x;
    if (i < EE) {
        int d = dst[i];
        int p = g_off[d] + atomicAdd(&g_cur[d], 1);
        g_csr[p] = src[i];
    }
}

__global__ void gstart_kernel(const int* __restrict__ gids) {
    int b = blockIdx.x * blockDim.x + threadIdx.x;
    if (b > BBG) return;
    int lo = 0, hi = NN;
    while (lo < hi) {
        int mid = (lo + hi) >> 1;
        if (gids[mid] < b) lo = mid + 1; else hi = mid;
    }
    g_gstart[b] = lo;
}

// ---------------- attention coefficients --------------------------------------
// att_s[n,h] = sum_d h[n, h*64+d]*a_src[h,d]; a_* flat [256] matches row layout.
__global__ void att_kernel(const float* __restrict__ h,
                           const float* __restrict__ a_src,
                           const float* __restrict__ a_dst) {
    int warp = (blockIdx.x * blockDim.x + threadIdx.x) >> 5;
    int lane = threadIdx.x & 31;
    if (warp >= NN) return;
    const float* row = h + (long)warp * HDIM;
    float ps[4] = {0, 0, 0, 0}, pd[4] = {0, 0, 0, 0};
#pragma unroll
    for (int i = 0; i < 8; i++) {
        int idx = lane + 32 * i;
        float v = row[idx];
        ps[i >> 1] += v * a_src[idx];
        pd[i >> 1] += v * a_dst[idx];
    }
#pragma unroll
    for (int o = 16; o; o >>= 1) {
#pragma unroll
        for (int hh = 0; hh < 4; hh++) {
            ps[hh] += __shfl_xor_sync(0xffffffffu, ps[hh], o);
            pd[hh] += __shfl_xor_sync(0xffffffffu, pd[hh], o);
        }
    }
    if (lane == 0) {
#pragma unroll
        for (int hh = 0; hh < 4; hh++) {
            g_atts[warp * 4 + hh] = ps[hh];
            g_attd[warp * 4 + hh] = pd[hh];
        }
    }
}

// ---------------- GAT aggregation: one warp per destination node --------------
__global__ void gat_agg(const float* __restrict__ h, float* __restrict__ out) {
    int node = (blockIdx.x * blockDim.x + threadIdx.x) >> 5;
    int lane = threadIdx.x & 31;
    if (node >= NN) return;
    const int s0 = g_off[node], s1 = g_off[node + 1];

    const float ad0 = g_attd[node * 4 + 0];
    const float ad1 = g_attd[node * 4 + 1];
    const float ad2 = g_attd[node * 4 + 2];
    const float ad3 = g_attd[node * 4 + 3];

    // pass 1: per-head max of leaky_relu(att_s[src]+att_d[dst]) (lane-parallel)
    float m0 = -1e30f, m1 = -1e30f, m2 = -1e30f, m3 = -1e30f;
    for (int e = s0 + lane; e < s1; e += 32) {
        int src = g_csr[e];
        float e0 = g_atts[src * 4 + 0] + ad0; e0 = e0 >= 0.f ? e0 : 0.2f * e0;
        float e1 = g_atts[src * 4 + 1] + ad1; e1 = e1 >= 0.f ? e1 : 0.2f * e1;
        float e2 = g_atts[src * 4 + 2] + ad2; e2 = e2 >= 0.f ? e2 : 0.2f * e2;
        float e3 = g_atts[src * 4 + 3] + ad3; e3 = e3 >= 0.f ? e3 : 0.2f * e3;
        m0 = fmaxf(m0, e0); m1 = fmaxf(m1, e1); m2 = fmaxf(m2, e2); m3 = fmaxf(m3, e3);
    }
#pragma unroll
    for (int o = 16; o; o >>= 1) {
        m0 = fmaxf(m0, __shfl_xor_sync(0xffffffffu, m0, o));
        m1 = fmaxf(m1, __shfl_xor_sync(0xffffffffu, m1, o));
        m2 = fmaxf(m2, __shfl_xor_sync(0xffffffffu, m2, o));
        m3 = fmaxf(m3, __shfl_xor_sync(0xffffffffu, m3, o));
    }

    // pass 2: weighted aggregation, lane owns dims lane+32*i (head = i>>1)
    float acc[8];
#pragma unroll
    for (int i = 0; i < 8; i++) acc[i] = 0.f;
    float den0 = 0.f, den1 = 0.f, den2 = 0.f, den3 = 0.f;

    for (int e = s0; e < s1; e++) {
        int src = g_csr[e];
        float e0 = g_atts[src * 4 + 0] + ad0; e0 = e0 >= 0.f ? e0 : 0.2f * e0;
        float e1 = g_atts[src * 4 + 1] + ad1; e1 = e1 >= 0.f ? e1 : 0.2f * e1;
        float e2 = g_atts[src * 4 + 2] + ad2; e2 = e2 >= 0.f ? e2 : 0.2f * e2;
        float e3 = g_atts[src * 4 + 3] + ad3; e3 = e3 >= 0.f ? e3 : 0.2f * e3;
        float w0 = __expf(e0 - m0), w1 = __expf(e1 - m1);
        float w2 = __expf(e2 - m2), w3 = __expf(e3 - m3);
        den0 += w0; den1 += w1; den2 += w2; den3 += w3;
        const float* hrow = h + (long)src * HDIM;
#pragma unroll
        for (int i = 0; i < 8; i++) {
            float w = (i < 2) ? w0 : (i < 4) ? w1 : (i < 6) ? w2 : w3;
            acc[i] += hrow[lane + 32 * i] * w;
        }
    }

#pragma unroll
    for (int i = 0; i < 8; i++) {
        float den = (i < 2) ? den0 : (i < 4) ? den1 : (i < 6) ? den2 : den3;
        float v = acc[i] / (den + 1e-9f);
        v = v > 0.f ? v : (__expf(v) - 1.0f);     // ELU(alpha=1)
        out[(long)node * HDIM + lane + 32 * i] = v;
    }
}

// ---------------- pooling + head ---------------------------------------------
__global__ void pool_kernel(const float* __restrict__ h) {
    int b = blockIdx.x;          // 512 blocks, 256 threads
    int d = threadIdx.x;
    int s = g_gstart[b], e = g_gstart[b + 1];
    float sum = 0.f;
    for (int n = s; n < e; n++) sum += h[(long)n * HDIM + d];
    float c = (float)((e - s) > 1 ? (e - s) : 1);
    g_pool[b * HDIM + d] = sum / c;
}

__global__ void final_kernel(const float* __restrict__ scores,
                             const float* __restrict__ W_out,
                             const float* __restrict__ b_out,
                             float* __restrict__ out) {
    int b = (blockIdx.x * blockDim.x + threadIdx.x) >> 5;
    int lane = threadIdx.x & 31;
    if (b >= BBG) return;
    float s = 0.f;
#pragma unroll
    for (int i = 0; i < 8; i++) {
        int d = lane + 32 * i;
        s += g_pool[b * HDIM + d] * W_out[d];
    }
#pragma unroll
    for (int o = 16; o; o >>= 1) s += __shfl_xor_sync(0xffffffffu, s, o);
    if (lane == 0) out[b] = s + scores[b] * W_out[HDIM] + b_out[0];
}

// ---------------- launch -------------------------------------------------------
extern "C" void kernel_launch(void* const* d_in, const int* in_sizes, int n_in,
                              void* d_out, int out_size) {
    const float* ligand_x  = (const float*)d_in[0];
    const float* protein_x = (const float*)d_in[1];
    const float* W_lig     = (const float*)d_in[2];
    const float* W_prot    = (const float*)d_in[3];
    const float* W1        = (const float*)d_in[4];
    const float* a1_src    = (const float*)d_in[5];
    const float* a1_dst    = (const float*)d_in[6];
    const float* W2        = (const float*)d_in[7];
    const float* a2_src    = (const float*)d_in[8];
    const float* a2_dst    = (const float*)d_in[9];
    const float* W_out     = (const float*)d_in[10];
    const float* b_out     = (const float*)d_in[11];
    const int*   edge_src  = (const int*)d_in[12];
    const int*   edge_dst  = (const int*)d_in[13];
    const int*   graph_ids = (const int*)d_in[14];
    const float* scores    = (const float*)d_in[15];
    float* out = (float*)d_out;

    void *p_cnt, *p_cur, *p_x, *p_h, *p_y;
    cudaGetSymbolAddress(&p_cnt, g_cnt);
    cudaGetSymbolAddress(&p_cur, g_cur);
    cudaGetSymbolAddress(&p_x, g_x);
    cudaGetSymbolAddress(&p_h, g_h);
    cudaGetSymbolAddress(&p_y, g_y);
    float* x = (float*)p_x;
    float* h = (float*)p_h;
    float* y = (float*)p_y;

    // ---- CSR build (dst-grouped incoming edge lists)
    cudaMemsetAsync(p_cnt, 0, NN * sizeof(int));
    cudaMemsetAsync(p_cur, 0, NN * sizeof(int));
    count_edges<<<(EE + 255) / 256, 256>>>(edge_dst);
    scan_kernel<<<1, 1024>>>();
    scatter_edges<<<(EE + 255) / 256, 256>>>(edge_src, edge_dst);
    gstart_kernel<<<(BBG + 256) / 256, 256>>>(graph_ids);

    // ---- input projections into shared hidden space
    {
        dim3 gl(HDIM / 128, (NLIG + 127) / 128);
        sgemm128<<<gl, 256>>>(ligand_x, W_lig, x, NLIG, HDIM, FLIG);
        dim3 gp(HDIM / 128, (NPROT + 127) / 128);
        sgemm128<<<gp, 256>>>(protein_x, W_prot, x + (long)NLIG * HDIM, NPROT, HDIM, FPROT);
    }

    const int warpBlocks = (NN * 32 + 255) / 256;
    dim3 gn(HDIM / 128, (NN + 127) / 128);

    // ---- GAT layer 1
    sgemm128<<<gn, 256>>>(x, W1, h, NN, HDIM, HDIM);
    att_kernel<<<warpBlocks, 256>>>(h, a1_src, a1_dst);
    gat_agg<<<warpBlocks, 256>>>(h, y);

    // ---- GAT layer 2
    sgemm128<<<gn, 256>>>(y, W2, h, NN, HDIM, HDIM);
    att_kernel<<<warpBlocks, 256>>>(h, a2_src, a2_dst);
    gat_agg<<<warpBlocks, 256>>>(h, x);   // reuse x as layer-2 output

    // ---- pooling + linear head
    pool_kernel<<<BBG, 256>>>(x);
    final_kernel<<<(BBG * 32 + 255) / 256, 256>>>(scores, W_out, b_out, out);
}

// round 3
// speedup vs baseline: 2.2168x; 2.2168x over previous
#include <cuda_runtime.h>
#include <cstdint>
#include <math.h>

#define NLIG  10000
#define NPROT 40000
#define NN    50000
#define EE    400000
#define BBG   512
#define HDIM  256
#define FLIG  74
#define FPROT 1280

// ---------------- scratch (static device globals; no runtime alloc) ----------
__device__ float g_x[NN * HDIM];
__device__ float g_h[NN * HDIM];
__device__ float g_y[NN * HDIM];
__device__ float g_Wt[256 * 1280];    // transposed weights [N,K]
__device__ float g_atts[NN * 4];
__device__ float g_attd[NN * 4];
__device__ int   g_cnt[NN];
__device__ int   g_cur[NN];
__device__ int   g_off[NN + 1];
__device__ int   g_csr[EE];
__device__ int   g_gstart[BBG + 1];
__device__ float g_pool[BBG * HDIM];

// ==================== helpers ====================
__device__ __forceinline__ uint32_t f2tf32(float x) {
    uint32_t r;
    asm("cvt.rna.tf32.f32 %0, %1;" : "=r"(r) : "f"(x));
    return r;
}

__device__ __forceinline__ void mma_tf32(float* c, const uint32_t* a, const uint32_t* b) {
    asm volatile("mma.sync.aligned.m16n8k8.row.col.f32.tf32.tf32.f32 "
                 "{%0,%1,%2,%3}, {%4,%5,%6,%7}, {%8,%9}, {%0,%1,%2,%3};"
                 : "+f"(c[0]), "+f"(c[1]), "+f"(c[2]), "+f"(c[3])
                 : "r"(a[0]), "r"(a[1]), "r"(a[2]), "r"(a[3]), "r"(b[0]), "r"(b[1]));
}

// swizzled smem read: tile stored [row][32] floats, col' = col ^ (4*(row&7))
__device__ __forceinline__ uint32_t ldsw(const uint32_t* base, int row, int col) {
    return base[row * 32 + (col ^ ((row & 7) * 4))];
}

// ==================== tf32 mma GEMM: C[M,256] = A[M,K] @ Bt[256,K]^T ==========
// 128x128 CTA tile, 8 warps (warp tile 32x64), BK=32, double-buffered smem.
// K must be a multiple of 32.  grid = (ceil(M/128), 2), 256 threads.
__global__ void __launch_bounds__(256) gemm_mma(const float* __restrict__ A,
                                                const float* __restrict__ Bt,
                                                float* __restrict__ C, int M, int K) {
    extern __shared__ float smem[];   // [2 buffers][A 4096 | B 4096]
    const int tid = threadIdx.x, wid = tid >> 5, lane = tid & 31;
    const int m0 = blockIdx.x * 128, n0 = blockIdx.y * 128;
    const int warp_m = (wid & 3) * 32, warp_n = (wid >> 2) * 64;
    const int lq = lane >> 2, lr = lane & 3;   // lane/4, lane%4

    const int srow = tid >> 1;                 // staging row 0..127
    const int skb  = (tid & 1) * 16;           // staging k base 0 or 16
    const int sx   = (srow & 7) * 4;           // swizzle for staging row
    const bool aval = (m0 + srow) < M;
    const float* arow = A  + (long)(m0 + srow) * K + skb;
    const float* brow = Bt + (long)(n0 + srow) * K + skb;

    float acc[2][8][4];
#pragma unroll
    for (int mt = 0; mt < 2; mt++)
#pragma unroll
        for (int nt = 0; nt < 8; nt++)
#pragma unroll
            for (int i = 0; i < 4; i++) acc[mt][nt][i] = 0.f;

    const int iters = K >> 5;

    float4 ga[4], gb[4];
    // prologue: load tile 0
#pragma unroll
    for (int j = 0; j < 4; j++) {
        ga[j] = aval ? *(const float4*)(arow + 4 * j) : make_float4(0.f, 0.f, 0.f, 0.f);
        gb[j] = *(const float4*)(brow + 4 * j);
    }
    {
        float* As = smem;
        float* Bs = smem + 4096;
#pragma unroll
        for (int j = 0; j < 4; j++) {
            uint32_t c = (skb + 4 * j) ^ sx;
            *(uint4*)(As + srow * 32 + c) = make_uint4(f2tf32(ga[j].x), f2tf32(ga[j].y),
                                                       f2tf32(ga[j].z), f2tf32(ga[j].w));
            *(uint4*)(Bs + srow * 32 + c) = make_uint4(f2tf32(gb[j].x), f2tf32(gb[j].y),
                                                       f2tf32(gb[j].z), f2tf32(gb[j].w));
        }
    }
    __syncthreads();

    for (int it = 0; it < iters; it++) {
        const bool more = (it + 1) < iters;
        if (more) {
            const float* ap = arow + (long)(it + 1) * 32;
            const float* bp = brow + (long)(it + 1) * 32;
#pragma unroll
            for (int j = 0; j < 4; j++) {
                ga[j] = aval ? *(const float4*)(ap + 4 * j) : make_float4(0.f, 0.f, 0.f, 0.f);
                gb[j] = *(const float4*)(bp + 4 * j);
            }
        }

        const uint32_t* As = (const uint32_t*)(smem + (it & 1) * 8192);
        const uint32_t* Bs = As + 4096;
#pragma unroll
        for (int ks = 0; ks < 4; ks++) {
            const int k0 = ks * 8;
            uint32_t af[2][4];
#pragma unroll
            for (int mt = 0; mt < 2; mt++) {
                int r = warp_m + mt * 16 + lq;
                af[mt][0] = ldsw(As, r,     k0 + lr);
                af[mt][1] = ldsw(As, r + 8, k0 + lr);
                af[mt][2] = ldsw(As, r,     k0 + 4 + lr);
                af[mt][3] = ldsw(As, r + 8, k0 + 4 + lr);
            }
#pragma unroll
            for (int nt = 0; nt < 8; nt++) {
                uint32_t bf[2];
                int rn = warp_n + nt * 8 + lq;
                bf[0] = ldsw(Bs, rn, k0 + lr);
                bf[1] = ldsw(Bs, rn, k0 + 4 + lr);
                mma_tf32(acc[0][nt], af[0], bf);
                mma_tf32(acc[1][nt], af[1], bf);
            }
        }

        if (more) {
            float* Asn = smem + ((it + 1) & 1) * 8192;
            float* Bsn = Asn + 4096;
#pragma unroll
            for (int j = 0; j < 4; j++) {
                uint32_t c = (skb + 4 * j) ^ sx;
                *(uint4*)(Asn + srow * 32 + c) = make_uint4(f2tf32(ga[j].x), f2tf32(ga[j].y),
                                                            f2tf32(ga[j].z), f2tf32(ga[j].w));
                *(uint4*)(Bsn + srow * 32 + c) = make_uint4(f2tf32(gb[j].x), f2tf32(gb[j].y),
                                                            f2tf32(gb[j].z), f2tf32(gb[j].w));
            }
            __syncthreads();
        }
    }

    // epilogue: c0 (row=lq, col=2*lr), c1 (+1), c2/c3 (row+8)
#pragma unroll
    for (int mt = 0; mt < 2; mt++) {
        int m = m0 + warp_m + mt * 16 + lq;
#pragma unroll
        for (int nt = 0; nt < 8; nt++) {
            int n = n0 + warp_n + nt * 8 + 2 * lr;
            if (m < M)
                *(float2*)(C + (long)m * 256 + n) = make_float2(acc[mt][nt][0], acc[mt][nt][1]);
            if (m + 8 < M)
                *(float2*)(C + (long)(m + 8) * 256 + n) = make_float2(acc[mt][nt][2], acc[mt][nt][3]);
        }
    }
}

// ---------------- weight transpose: Wt[n][k] = W[k][n] -----------------------
__global__ void transpose_kernel(const float* __restrict__ W, float* __restrict__ Wt,
                                 int K, int N) {
    __shared__ float t[32][33];
    int kb = blockIdx.y * 32, nb = blockIdx.x * 32;
#pragma unroll
    for (int i = 0; i < 32; i += 8) {
        int k = kb + threadIdx.y + i, n = nb + threadIdx.x;
        if (k < K && n < N) t[threadIdx.y + i][threadIdx.x] = W[(long)k * N + n];
    }
    __syncthreads();
#pragma unroll
    for (int i = 0; i < 32; i += 8) {
        int n = nb + threadIdx.y + i, k = kb + threadIdx.x;
        if (n < N && k < K) Wt[(long)n * K + k] = t[threadIdx.x][threadIdx.y + i];
    }
}

// ---------------- fp32 SGEMM (ligand only, K=74) ------------------------------
__global__ void sgemm128(const float* __restrict__ A, const float* __restrict__ B,
                         float* __restrict__ C, int M, int N, int K) {
    __shared__ float As[8][128];
    __shared__ float Bs[8][128];
    const int tid = threadIdx.x;
    const int tx = tid & 15;
    const int ty = tid >> 4;
    const int rowBase = blockIdx.y * 128;
    const int colBase = blockIdx.x * 128;

    const int aRow = tid >> 1;
    const int aCol0 = (tid & 1) * 4;
    const int bRow = tid >> 5;
    const int bCol = (tid & 31) * 4;

    float acc[8][8];
#pragma unroll
    for (int i = 0; i < 8; i++)
#pragma unroll
        for (int j = 0; j < 8; j++) acc[i][j] = 0.f;

    for (int k0 = 0; k0 < K; k0 += 8) {
        {
            int gr = rowBase + aRow;
#pragma unroll
            for (int j = 0; j < 4; j++) {
                int k = k0 + aCol0 + j;
                float v = 0.f;
                if (gr < M && k < K) v = A[(long)gr * K + k];
                As[aCol0 + j][aRow] = v;
            }
        }
        {
            int k = k0 + bRow;
            float4 v = make_float4(0.f, 0.f, 0.f, 0.f);
            if (k < K) v = *(const float4*)(B + (long)k * N + colBase + bCol);
            *(float4*)&Bs[bRow][bCol] = v;
        }
        __syncthreads();
#pragma unroll
        for (int kk = 0; kk < 8; kk++) {
            float a[8], b[8];
#pragma unroll
            for (int i = 0; i < 8; i++) a[i] = As[kk][ty * 8 + i];
#pragma unroll
            for (int j = 0; j < 8; j++) b[j] = Bs[kk][tx * 8 + j];
#pragma unroll
            for (int i = 0; i < 8; i++)
#pragma unroll
                for (int j = 0; j < 8; j++) acc[i][j] += a[i] * b[j];
        }
        __syncthreads();
    }

#pragma unroll
    for (int i = 0; i < 8; i++) {
        int gr = rowBase + ty * 8 + i;
        if (gr >= M) continue;
        float* crow = C + (long)gr * N + colBase + tx * 8;
        *(float4*)(crow)     = make_float4(acc[i][0], acc[i][1], acc[i][2], acc[i][3]);
        *(float4*)(crow + 4) = make_float4(acc[i][4], acc[i][5], acc[i][6], acc[i][7]);
    }
}

// ---------------- CSR build ----------------
__global__ void count_edges(const int* __restrict__ dst) {
    int i = blockIdx.x * blockDim.x + threadIdx.x;
    if (i < EE) atomicAdd(&g_cnt[dst[i]], 1);
}

__global__ void scan_kernel() {
    __shared__ int wsum[32];
    const int tid = threadIdx.x, lane = tid & 31, wid = tid >> 5;
    int carry = 0;
    for (int base = 0; base < NN; base += 1024) {
        int i = base + tid;
        int v = (i < NN) ? g_cnt[i] : 0;
        int x = v;
#pragma unroll
        for (int o = 1; o < 32; o <<= 1) {
            int y = __shfl_up_sync(0xffffffffu, x, o);
            if (lane >= o) x += y;
        }
        if (lane == 31) wsum[wid] = x;
        __syncthreads();
        if (wid == 0) {
            int s = wsum[lane];
#pragma unroll
            for (int o = 1; o < 32; o <<= 1) {
                int y = __shfl_up_sync(0xffffffffu, s, o);
                if (lane >= o) s += y;
            }
            wsum[lane] = s;
        }
        __syncthreads();
        int woff = wid ? wsum[wid - 1] : 0;
        if (i < NN) g_off[i] = carry + woff + x - v;
        int total = wsum[31];
        __syncthreads();
        carry += total;
    }
    if (tid == 0) g_off[NN] = carry;
}

__global__ void scatter_edges(const int* __restrict__ src, const int* __restrict__ dst) {
    int i = blockIdx.x * blockDim.x + threadIdx.x;
    if (i < EE) {
        int d = dst[i];
        int p = g_off[d] + atomicAdd(&g_cur[d], 1);
        g_csr[p] = src[i];
    }
}

__global__ void gstart_kernel(const int* __restrict__ gids) {
    int b = blockIdx.x * blockDim.x + threadIdx.x;
    if (b > BBG) return;
    int lo = 0, hi = NN;
    while (lo < hi) {
        int mid = (lo + hi) >> 1;
        if (gids[mid] < b) lo = mid + 1; else hi = mid;
    }
    g_gstart[b] = lo;
}

// ---------------- attention coefficients --------------------------------------
__global__ void att_kernel(const float* __restrict__ h,
                           const float* __restrict__ a_src,
                           const float* __restrict__ a_dst) {
    int warp = (blockIdx.x * blockDim.x + threadIdx.x) >> 5;
    int lane = threadIdx.x & 31;
    if (warp >= NN) return;
    const float* row = h + (long)warp * HDIM;
    float ps[4] = {0, 0, 0, 0}, pd[4] = {0, 0, 0, 0};
#pragma unroll
    for (int i = 0; i < 8; i++) {
        int idx = lane + 32 * i;
        float v = row[idx];
        ps[i >> 1] += v * a_src[idx];
        pd[i >> 1] += v * a_dst[idx];
    }
#pragma unroll
    for (int o = 16; o; o >>= 1) {
#pragma unroll
        for (int hh = 0; hh < 4; hh++) {
            ps[hh] += __shfl_xor_sync(0xffffffffu, ps[hh], o);
            pd[hh] += __shfl_xor_sync(0xffffffffu, pd[hh], o);
        }
    }
    if (lane == 0) {
#pragma unroll
        for (int hh = 0; hh < 4; hh++) {
            g_atts[warp * 4 + hh] = ps[hh];
            g_attd[warp * 4 + hh] = pd[hh];
        }
    }
}

// ---------------- GAT aggregation: one warp per destination node --------------
__global__ void gat_agg(const float* __restrict__ h, float* __restrict__ out) {
    int node = (blockIdx.x * blockDim.x + threadIdx.x) >> 5;
    int lane = threadIdx.x & 31;
    if (node >= NN) return;
    const int s0 = g_off[node], s1 = g_off[node + 1];

    const float ad0 = g_attd[node * 4 + 0];
    const float ad1 = g_attd[node * 4 + 1];
    const float ad2 = g_attd[node * 4 + 2];
    const float ad3 = g_attd[node * 4 + 3];

    float m0 = -1e30f, m1 = -1e30f, m2 = -1e30f, m3 = -1e30f;
    for (int e = s0 + lane; e < s1; e += 32) {
        int src = g_csr[e];
        float e0 = g_atts[src * 4 + 0] + ad0; e0 = e0 >= 0.f ? e0 : 0.2f * e0;
        float e1 = g_atts[src * 4 + 1] + ad1; e1 = e1 >= 0.f ? e1 : 0.2f * e1;
        float e2 = g_atts[src * 4 + 2] + ad2; e2 = e2 >= 0.f ? e2 : 0.2f * e2;
        float e3 = g_atts[src * 4 + 3] + ad3; e3 = e3 >= 0.f ? e3 : 0.2f * e3;
        m0 = fmaxf(m0, e0); m1 = fmaxf(m1, e1); m2 = fmaxf(m2, e2); m3 = fmaxf(m3, e3);
    }
#pragma unroll
    for (int o = 16; o; o >>= 1) {
        m0 = fmaxf(m0, __shfl_xor_sync(0xffffffffu, m0, o));
        m1 = fmaxf(m1, __shfl_xor_sync(0xffffffffu, m1, o));
        m2 = fmaxf(m2, __shfl_xor_sync(0xffffffffu, m2, o));
        m3 = fmaxf(m3, __shfl_xor_sync(0xffffffffu, m3, o));
    }

    float acc[8];
#pragma unroll
    for (int i = 0; i < 8; i++) acc[i] = 0.f;
    float den0 = 0.f, den1 = 0.f, den2 = 0.f, den3 = 0.f;

    for (int e = s0; e < s1; e++) {
        int src = g_csr[e];
        float e0 = g_atts[src * 4 + 0] + ad0; e0 = e0 >= 0.f ? e0 : 0.2f * e0;
        float e1 = g_atts[src * 4 + 1] + ad1; e1 = e1 >= 0.f ? e1 : 0.2f * e1;
        float e2 = g_atts[src * 4 + 2] + ad2; e2 = e2 >= 0.f ? e2 : 0.2f * e2;
        float e3 = g_atts[src * 4 + 3] + ad3; e3 = e3 >= 0.f ? e3 : 0.2f * e3;
        float w0 = __expf(e0 - m0), w1 = __expf(e1 - m1);
        float w2 = __expf(e2 - m2), w3 = __expf(e3 - m3);
        den0 += w0; den1 += w1; den2 += w2; den3 += w3;
        const float* hrow = h + (long)src * HDIM;
#pragma unroll
        for (int i = 0; i < 8; i++) {
            float w = (i < 2) ? w0 : (i < 4) ? w1 : (i < 6) ? w2 : w3;
            acc[i] += hrow[lane + 32 * i] * w;
        }
    }

#pragma unroll
    for (int i = 0; i < 8; i++) {
        float den = (i < 2) ? den0 : (i < 4) ? den1 : (i < 6) ? den2 : den3;
        float v = acc[i] / (den + 1e-9f);
        v = v > 0.f ? v : (__expf(v) - 1.0f);
        out[(long)node * HDIM + lane + 32 * i] = v;
    }
}

// ---------------- pooling + head ---------------------------------------------
__global__ void pool_kernel(const float* __restrict__ h) {
    int b = blockIdx.x;
    int d = threadIdx.x;
    int s = g_gstart[b], e = g_gstart[b + 1];
    float sum = 0.f;
    for (int n = s; n < e; n++) sum += h[(long)n * HDIM + d];
    float c = (float)((e - s) > 1 ? (e - s) : 1);
    g_pool[b * HDIM + d] = sum / c;
}

__global__ void final_kernel(const float* __restrict__ scores,
                             const float* __restrict__ W_out,
                             const float* __restrict__ b_out,
                             float* __restrict__ out) {
    int b = (blockIdx.x * blockDim.x + threadIdx.x) >> 5;
    int lane = threadIdx.x & 31;
    if (b >= BBG) return;
    float s = 0.f;
#pragma unroll
    for (int i = 0; i < 8; i++) {
        int d = lane + 32 * i;
        s += g_pool[b * HDIM + d] * W_out[d];
    }
#pragma unroll
    for (int o = 16; o; o >>= 1) s += __shfl_xor_sync(0xffffffffu, s, o);
    if (lane == 0) out[b] = s + scores[b] * W_out[HDIM] + b_out[0];
}

// ---------------- launch -------------------------------------------------------
extern "C" void kernel_launch(void* const* d_in, const int* in_sizes, int n_in,
                              void* d_out, int out_size) {
    const float* ligand_x  = (const float*)d_in[0];
    const float* protein_x = (const float*)d_in[1];
    const float* W_lig     = (const float*)d_in[2];
    const float* W_prot    = (const float*)d_in[3];
    const float* W1        = (const float*)d_in[4];
    const float* a1_src    = (const float*)d_in[5];
    const float* a1_dst    = (const float*)d_in[6];
    const float* W2        = (const float*)d_in[7];
    const float* a2_src    = (const float*)d_in[8];
    const float* a2_dst    = (const float*)d_in[9];
    const float* W_out     = (const float*)d_in[10];
    const float* b_out     = (const float*)d_in[11];
    const int*   edge_src  = (const int*)d_in[12];
    const int*   edge_dst  = (const int*)d_in[13];
    const int*   graph_ids = (const int*)d_in[14];
    const float* scores    = (const float*)d_in[15];
    float* out = (float*)d_out;

    void *p_cnt, *p_cur, *p_x, *p_h, *p_y, *p_wt;
    cudaGetSymbolAddress(&p_cnt, g_cnt);
    cudaGetSymbolAddress(&p_cur, g_cur);
    cudaGetSymbolAddress(&p_x, g_x);
    cudaGetSymbolAddress(&p_h, g_h);
    cudaGetSymbolAddress(&p_y, g_y);
    cudaGetSymbolAddress(&p_wt, g_Wt);
    float* x  = (float*)p_x;
    float* h  = (float*)p_h;
    float* y  = (float*)p_y;
    float* Wt = (float*)p_wt;

    const int GEMM_SMEM = 2 * 8192 * sizeof(float);   // 64 KB
    cudaFuncSetAttribute(gemm_mma, cudaFuncAttributeMaxDynamicSharedMemorySize, GEMM_SMEM);

    // ---- CSR build (dst-grouped incoming edge lists)
    cudaMemsetAsync(p_cnt, 0, NN * sizeof(int));
    cudaMemsetAsync(p_cur, 0, NN * sizeof(int));
    count_edges<<<(EE + 255) / 256, 256>>>(edge_dst);
    scan_kernel<<<1, 1024>>>();
    scatter_edges<<<(EE + 255) / 256, 256>>>(edge_src, edge_dst);
    gstart_kernel<<<(BBG + 256) / 256, 256>>>(graph_ids);

    // ---- input projections
    {
        dim3 gl(HDIM / 128, (NLIG + 127) / 128);
        sgemm128<<<gl, 256>>>(ligand_x, W_lig, x, NLIG, HDIM, FLIG);
        transpose_kernel<<<dim3(HDIM / 32, FPROT / 32), dim3(32, 8)>>>(W_prot, Wt, FPROT, HDIM);
        dim3 gp((NPROT + 127) / 128, 2);
        gemm_mma<<<gp, 256, GEMM_SMEM>>>(protein_x, Wt, x + (long)NLIG * HDIM, NPROT, FPROT);
    }

    const int warpBlocks = (NN * 32 + 255) / 256;
    dim3 gn((NN + 127) / 128, 2);

    // ---- GAT layer 1
    transpose_kernel<<<dim3(HDIM / 32, HDIM / 32), dim3(32, 8)>>>(W1, Wt, HDIM, HDIM);
    gemm_mma<<<gn, 256, GEMM_SMEM>>>(x, Wt, h, NN, HDIM);
    att_kernel<<<warpBlocks, 256>>>(h, a1_src, a1_dst);
    gat_agg<<<warpBlocks, 256>>>(h, y);

    // ---- GAT layer 2
    transpose_kernel<<<dim3(HDIM / 32, HDIM / 32), dim3(32, 8)>>>(W2, Wt, HDIM, HDIM);
    gemm_mma<<<gn, 256, GEMM_SMEM>>>(y, Wt, h, NN, HDIM);
    att_kernel<<<warpBlocks, 256>>>(h, a2_src, a2_dst);
    gat_agg<<<warpBlocks, 256>>>(h, x);

    // ---- pooling + linear head
    pool_kernel<<<BBG, 256>>>(x);
    final_kernel<<<(BBG * 32 + 255) / 256, 256>>>(scores, W_out, b_out, out);
}